// round 13
// baseline (speedup 1.0000x reference)
#include <cuda_runtime.h>
#include <cuda_bf16.h>
#include <math.h>
#include <cstdint>

#define NN   50000
#define EE   800000
#define HH   128
#define GG   64
#define LL   6
#define OUTC 10
#define EPS  1e-5f
#define NPART 98            // ceil(NN/512)
#define TM   32
#define TILES32 ((NN + TM - 1) / TM)
#define GEMM_GRID 148       // 1 CTA/SM persistent
#define BP   136            // bf16 smem pitch (272B rows)

typedef unsigned long long ull;

// ---------------- scratch (device globals) ----------------------------------
__device__ float g_buf [NN * HH];
__device__ float g_lin [NN * HH];
__device__ int   g_cnt [NN];
__device__ int   g_cur [NN];
__device__ int   g_rowptr[NN + 1];
__device__ int   g_part[NPART];
__device__ int   g_col [EE];
__device__ float g_wgt [EE];
__device__ float g_dinv[NN];
__device__ float g_selfw[NN];
__device__ float g_stats[(LL - 1) * 2 * HH];
__device__ float g_pooled[GG * HH];
__device__ int   g_pcnt[GG];

// ---------------- mma / ldmatrix helpers -------------------------------------
__device__ __forceinline__ uint32_t smem_u32(const void* p) {
    uint32_t a;
    asm("{ .reg .u64 t; cvta.to.shared.u64 t, %1; cvt.u32.u64 %0, t; }" : "=r"(a) : "l"(p));
    return a;
}
__device__ __forceinline__ void ldmx4(uint32_t& r0, uint32_t& r1, uint32_t& r2,
                                      uint32_t& r3, uint32_t a) {
    asm volatile("ldmatrix.sync.aligned.m8n8.x4.shared.b16 {%0,%1,%2,%3}, [%4];"
                 : "=r"(r0), "=r"(r1), "=r"(r2), "=r"(r3) : "r"(a));
}
__device__ __forceinline__ void mma_bf16(float* c, const uint32_t* a,
                                         uint32_t b0, uint32_t b1) {
    asm volatile("mma.sync.aligned.m16n8k16.row.col.f32.bf16.bf16.f32 "
                 "{%0,%1,%2,%3}, {%4,%5,%6,%7}, {%8,%9}, {%0,%1,%2,%3};"
                 : "+f"(c[0]), "+f"(c[1]), "+f"(c[2]), "+f"(c[3])
                 : "r"(a[0]), "r"(a[1]), "r"(a[2]), "r"(a[3]), "r"(b0), "r"(b1));
}
__device__ __forceinline__ uint32_t pack_hi(float x, float y) {
    __nv_bfloat162 h(__float2bfloat16_rn(x), __float2bfloat16_rn(y));
    return *(uint32_t*)&h;
}
__device__ __forceinline__ uint32_t pack_lo(float x, float y) {
    __nv_bfloat16 hx = __float2bfloat16_rn(x);
    __nv_bfloat16 hy = __float2bfloat16_rn(y);
    __nv_bfloat162 l(__float2bfloat16_rn(x - __bfloat162float(hx)),
                     __float2bfloat16_rn(y - __bfloat162float(hy)));
    return *(uint32_t*)&l;
}

// ---------------- graph preprocessing ---------------------------------------
__global__ void k_zero_counts() {
    int i = blockIdx.x * blockDim.x + threadIdx.x;
    if (i < NN) { g_cnt[i] = 0; g_cur[i] = 0; }
    if (i < (LL - 1) * 2 * HH) g_stats[i] = 0.f;
    if (i < GG * HH) g_pooled[i] = 0.f;
}

__global__ void k_hist(const int* __restrict__ dst) {
    int i = blockIdx.x * blockDim.x + threadIdx.x;
    if (i < EE / 4) {
        int4 d = ((const int4*)dst)[i];
        atomicAdd(&g_cnt[d.x], 1);
        atomicAdd(&g_cnt[d.y], 1);
        atomicAdd(&g_cnt[d.z], 1);
        atomicAdd(&g_cnt[d.w], 1);
    }
}

__global__ void k_scan_local() {
    __shared__ int wsum[16];
    int t = threadIdx.x;                 // 512
    int i = blockIdx.x * 512 + t;
    int v = (i < NN) ? g_cnt[i] : 0;
    int lane = t & 31, w = t >> 5;
    int x = v;
#pragma unroll
    for (int off = 1; off < 32; off <<= 1) {
        int y = __shfl_up_sync(0xffffffff, x, off);
        if (lane >= off) x += y;
    }
    if (lane == 31) wsum[w] = x;
    __syncthreads();
    if (w == 0) {
        int s = (lane < 16) ? wsum[lane] : 0;
#pragma unroll
        for (int off = 1; off < 16; off <<= 1) {
            int y = __shfl_up_sync(0xffffffff, s, off);
            if (lane >= off) s += y;
        }
        if (lane < 16) wsum[lane] = s;
    }
    __syncthreads();
    int incl = x + (w > 0 ? wsum[w - 1] : 0);
    if (i < NN) g_rowptr[i + 1] = incl;
    if (t == 511) g_part[blockIdx.x] = incl;
}

__global__ void k_scan_part() {
    __shared__ int wsum[4];
    int t = threadIdx.x;                 // 128
    int lane = t & 31, w = t >> 5;
    int v = (t < NPART) ? g_part[t] : 0;
    int x = v;
#pragma unroll
    for (int off = 1; off < 32; off <<= 1) {
        int y = __shfl_up_sync(0xffffffff, x, off);
        if (lane >= off) x += y;
    }
    if (lane == 31) wsum[w] = x;
    __syncthreads();
    if (w == 0 && lane < 4) {
        int s = wsum[lane];
#pragma unroll
        for (int off = 1; off < 4; off <<= 1) {
            int y = __shfl_up_sync(0x0000000f, s, off);
            if (lane >= off) s += y;
        }
        wsum[lane] = s;
    }
    __syncthreads();
    int incl = x + (w > 0 ? wsum[w - 1] : 0);
    if (t < NPART) g_part[t] = incl - v;   // exclusive
}

__global__ void k_scan_add() {
    int i = blockIdx.x * blockDim.x + threadIdx.x;
    if (i < NN) g_rowptr[i + 1] += g_part[i >> 9];
    if (i == 0) g_rowptr[0] = 0;
}

__global__ void k_dinv() {
    int i = blockIdx.x * blockDim.x + threadIdx.x;
    if (i < NN) {
        float deg = (float)(g_cnt[i] + 1);
        g_dinv[i] = rsqrtf(deg);
        g_selfw[i] = 1.f / deg;
    }
}

__global__ void k_scatter(const int* __restrict__ src, const int* __restrict__ dst) {
    int i = blockIdx.x * blockDim.x + threadIdx.x;
    if (i < EE) {
        int s = src[i], d = dst[i];
        int p = atomicAdd(&g_cur[d], 1);
        int idx = g_rowptr[d] + p;
        g_col[idx] = s;
        g_wgt[idx] = g_dinv[s] * g_dinv[d];
    }
}

// ---------------- tensor-core GEMM: Y = act(X) @ W ---------------------------
// mma.sync m16n8k16 bf16, 3-pass split. 32-row tiles (better tail balance:
// 1563 tiles / 148 CTAs -> 4% imbalance vs 13.6% at 64 rows). Warp = 16 rows
// x 32 cols; B fragments register-resident for the CTA lifetime; next tile's
// X rows prefetched into registers.
#define SM_BHI  0
#define SM_BLO  (SM_BHI + HH * BP * 2)
#define SM_XHI  (SM_BLO + HH * BP * 2)
#define SM_XLO  (SM_XHI + TM * BP * 2)
#define SM_SC   (SM_XLO + TM * BP * 2)
#define SM_SH   (SM_SC + 512)
#define SMEM_TC (SM_SH + 512)

__global__ __launch_bounds__(256, 1)
void k_gemm(const float* __restrict__ X, const float* __restrict__ W,
            float* __restrict__ Y,
            const float* __restrict__ stats,
            const float* __restrict__ gamma, const float* __restrict__ beta,
            int bn) {
    extern __shared__ char smem[];
    __nv_bfloat16* Bh = (__nv_bfloat16*)(smem + SM_BHI);
    __nv_bfloat16* Bl = (__nv_bfloat16*)(smem + SM_BLO);
    float* sc = (float*)(smem + SM_SC);
    float* shf = (float*)(smem + SM_SH);

    int tid = threadIdx.x;
    int lr = tid >> 3;                    // fill row 0..31
    int kq0 = tid & 7;                    // fill float4 phase

    // ---- prefetch first tile into registers ----
    float4 pf[4];
    {
        int grow = blockIdx.x * TM + lr;
        bool rv = grow < NN;
        const float4* Xg = (const float4*)(X + (size_t)(rv ? grow : 0) * HH);
#pragma unroll
        for (int i = 0; i < 4; i++)
            pf[i] = rv ? Xg[kq0 + i * 8] : make_float4(0.f, 0.f, 0.f, 0.f);
    }

    if (bn && tid < HH) {
        float mu  = stats[tid] * (1.f / NN);
        float var = stats[HH + tid] * (1.f / NN) - mu * mu;
        float s = rsqrtf(var + EPS) * gamma[tid];
        sc[tid] = s;
        shf[tid] = beta[tid] - mu * s;
    }

    {   // split W into Bt[n][k] hi/lo (once per CTA)
        const float4* W4 = (const float4*)W;
        for (int i = tid; i < HH * 32; i += 256) {
            int k = i >> 5, n4 = i & 31;
            float4 v = W4[k * 32 + n4];
            const float* vv = (const float*)&v;
#pragma unroll
            for (int j = 0; j < 4; j++) {
                int n = n4 * 4 + j;
                __nv_bfloat16 hi = __float2bfloat16_rn(vv[j]);
                Bh[n * BP + k] = hi;
                Bl[n * BP + k] = __float2bfloat16_rn(vv[j] - __bfloat162float(hi));
            }
        }
    }
    __syncthreads();

    uint32_t xh_u = smem_u32(smem + SM_XHI);
    uint32_t xl_u = smem_u32(smem + SM_XLO);
    uint32_t bh_u = smem_u32(smem + SM_BHI);
    uint32_t bl_u = smem_u32(smem + SM_BLO);

    int warp = tid >> 5, lane = tid & 31;
    int mrow = (warp & 1) * 16;           // 2 row groups of 16
    int ncol = (warp >> 1) * 32;          // 4 col groups of 32

    int aj = lane >> 3, ar = lane & 7;
    int a_rb  = ((aj & 1) << 3) + ar;
    int a_kad = (aj >> 1) << 3;
    int b_rowoff = ((aj >> 1) << 3) + ar;
    int b_kad = (aj & 1) << 3;

    // ---- preload ALL B fragments for this warp's 32 cols ----
    uint32_t bhr[8][2][4], blr[8][2][4];
#pragma unroll
    for (int ks = 0; ks < 8; ks++)
#pragma unroll
        for (int ng = 0; ng < 2; ng++) {
            int n0 = ncol + 16 * ng;
            uint32_t boff = (uint32_t)(((n0 + b_rowoff) * BP + ks * 16 + b_kad) * 2);
            ldmx4(bhr[ks][ng][0], bhr[ks][ng][1], bhr[ks][ng][2], bhr[ks][ng][3], bh_u + boff);
            ldmx4(blr[ks][ng][0], blr[ks][ng][1], blr[ks][ng][2], blr[ks][ng][3], bl_u + boff);
        }

    for (int tile = blockIdx.x; tile < TILES32; tile += gridDim.x) {
        int row0 = tile * TM;

        {   // fill X hi/lo tiles from prefetched registers (BN/ReLU fused)
#pragma unroll
            for (int i = 0; i < 4; i++) {
                int m = kq0 + i * 8;
                float4 v = pf[i];
                if (bn) {
                    int ch = 4 * m;
                    v.x = fmaxf(v.x * sc[ch]     + shf[ch],     0.f);
                    v.y = fmaxf(v.y * sc[ch + 1] + shf[ch + 1], 0.f);
                    v.z = fmaxf(v.z * sc[ch + 2] + shf[ch + 2], 0.f);
                    v.w = fmaxf(v.w * sc[ch + 3] + shf[ch + 3], 0.f);
                }
                uint2 hp, lp;
                hp.x = pack_hi(v.x, v.y); hp.y = pack_hi(v.z, v.w);
                lp.x = pack_lo(v.x, v.y); lp.y = pack_lo(v.z, v.w);
                *(uint2*)(smem + SM_XHI + (lr * BP + 4 * m) * 2) = hp;
                *(uint2*)(smem + SM_XLO + (lr * BP + 4 * m) * 2) = lp;
            }
        }

        {   // prefetch next tile's rows (hidden behind the mma)
            int ntile = tile + gridDim.x;
            if (ntile < TILES32) {
                int grow = ntile * TM + lr;
                bool rv = grow < NN;
                const float4* Xg = (const float4*)(X + (size_t)(rv ? grow : 0) * HH);
#pragma unroll
                for (int i = 0; i < 4; i++)
                    pf[i] = rv ? Xg[kq0 + i * 8] : make_float4(0.f, 0.f, 0.f, 0.f);
            }
        }
        __syncthreads();

        float c[2][2][4];
#pragma unroll
        for (int ng = 0; ng < 2; ng++)
#pragma unroll
            for (int nh = 0; nh < 2; nh++)
#pragma unroll
                for (int j = 0; j < 4; j++) c[ng][nh][j] = 0.f;

#pragma unroll
        for (int ks = 0; ks < 8; ks++) {
            int k0 = ks * 16;
            uint32_t ahi[4], alo[4];
            uint32_t aoff = (uint32_t)(((mrow + a_rb) * BP + k0 + a_kad) * 2);
            ldmx4(ahi[0], ahi[1], ahi[2], ahi[3], xh_u + aoff);
            ldmx4(alo[0], alo[1], alo[2], alo[3], xl_u + aoff);
#pragma unroll
            for (int ng = 0; ng < 2; ng++) {
                const uint32_t* bh = bhr[ks][ng];
                const uint32_t* bl = blr[ks][ng];
                mma_bf16(c[ng][0], ahi, bh[0], bh[1]);
                mma_bf16(c[ng][0], alo, bh[0], bh[1]);
                mma_bf16(c[ng][0], ahi, bl[0], bl[1]);
                mma_bf16(c[ng][1], ahi, bh[2], bh[3]);
                mma_bf16(c[ng][1], alo, bh[2], bh[3]);
                mma_bf16(c[ng][1], ahi, bl[2], bl[3]);
            }
        }

        {   // epilogue: c -> Y (fp32)
            int cb = 2 * (lane & 3);
            int rowin = lane >> 2;
            int m1 = row0 + mrow + rowin;
            int m2 = m1 + 8;
            bool v1 = m1 < NN, v2 = m2 < NN;
#pragma unroll
            for (int ng = 0; ng < 2; ng++)
#pragma unroll
                for (int nh = 0; nh < 2; nh++) {
                    int n0 = ncol + 16 * ng + 8 * nh + cb;
                    float* cc = c[ng][nh];
                    if (v1) *(float2*)(Y + (size_t)m1 * HH + n0) = make_float2(cc[0], cc[1]);
                    if (v2) *(float2*)(Y + (size_t)m2 * HH + n0) = make_float2(cc[2], cc[3]);
                }
        }
        __syncthreads();   // X tile reuse barrier
    }
}

// ---------------- aggregation (fp32 gather) + fused BN stats -----------------
__global__ __launch_bounds__(256)
void k_agg(const float* __restrict__ hlin, const float* __restrict__ bias,
           float* __restrict__ hout, float* __restrict__ stats, int do_stats) {
    int lane = threadIdx.x & 31;
    int warp = threadIdx.x >> 5;
    int gw = blockIdx.x * 8 + warp;
    int nw = gridDim.x * 8;

    const float4* h4 = (const float4*)hlin;
    float4 b4 = ((const float4*)bias)[lane];

    float4 s1 = make_float4(0.f, 0.f, 0.f, 0.f);
    float4 s2 = make_float4(0.f, 0.f, 0.f, 0.f);

    for (int n = gw; n < NN; n += nw) {
        int beg = g_rowptr[n], end = g_rowptr[n + 1];
        float4 acc = make_float4(0.f, 0.f, 0.f, 0.f);
        int e = beg;
        while (e < end) {
            int m2 = end - e; if (m2 > 8) m2 = 8;
            int   cc[8];
            float ww[8];
#pragma unroll
            for (int j = 0; j < 8; j++)
                if (j < m2) { cc[j] = g_col[e + j]; ww[j] = g_wgt[e + j]; }
#pragma unroll
            for (int j = 0; j < 8; j++)
                if (j < m2) {
                    float4 v = h4[(size_t)cc[j] * 32 + lane];
                    float w = ww[j];
                    acc.x += v.x * w; acc.y += v.y * w;
                    acc.z += v.z * w; acc.w += v.w * w;
                }
            e += m2;
        }
        float sw = g_selfw[n];
        float4 sf = h4[(size_t)n * 32 + lane];
        float4 o;
        o.x = acc.x + sf.x * sw + b4.x;
        o.y = acc.y + sf.y * sw + b4.y;
        o.z = acc.z + sf.z * sw + b4.z;
        o.w = acc.w + sf.w * sw + b4.w;
        ((float4*)hout)[(size_t)n * 32 + lane] = o;
        if (do_stats) {
            s1.x += o.x; s1.y += o.y; s1.z += o.z; s1.w += o.w;
            s2.x += o.x * o.x; s2.y += o.y * o.y;
            s2.z += o.z * o.z; s2.w += o.w * o.w;
        }
    }

    if (do_stats) {
        __shared__ float red[8][2 * HH];
        float* r = red[warp];
        int c = lane * 4;
        r[c] = s1.x; r[c + 1] = s1.y; r[c + 2] = s1.z; r[c + 3] = s1.w;
        r[HH + c] = s2.x; r[HH + c + 1] = s2.y;
        r[HH + c + 2] = s2.z; r[HH + c + 3] = s2.w;
        __syncthreads();
        int t = threadIdx.x;
        float s = 0.f;
#pragma unroll
        for (int w2 = 0; w2 < 8; w2++) s += red[w2][t];
        atomicAdd(&stats[t], s);
    }
}

// ---------------- global mean pool (batch sorted, 4-way split) ---------------
__device__ __forceinline__ int lowerb(const int* a, int n, int key) {
    int lo = 0, hi = n;
    while (lo < hi) {
        int m = (lo + hi) >> 1;
        if (a[m] < key) lo = m + 1; else hi = m;
    }
    return lo;
}

__global__ void k_pool(const float* __restrict__ h, const int* __restrict__ batch) {
    int g = blockIdx.x;      // 64
    int sub = blockIdx.y;    // 4
    int c = threadIdx.x;     // 128
    int lo = lowerb(batch, NN, g);
    int hi = lowerb(batch, NN, g + 1);
    float s = 0.f;
    for (int i = lo + sub; i < hi; i += 4) s += h[(size_t)i * HH + c];
    atomicAdd(&g_pooled[g * HH + c], s);
    if (sub == 0 && c == 0) g_pcnt[g] = hi - lo;
}

// ---------------- fused prediction head (one CTA) ----------------------------
#define HEAD_SMEM (2 * GG * HH * (int)sizeof(float))
__global__ __launch_bounds__(1024, 1)
void k_head(const float* __restrict__ W1, const float* __restrict__ b1,
            const float* __restrict__ bng, const float* __restrict__ bnb,
            const float* __restrict__ W2, const float* __restrict__ b2,
            const float* __restrict__ W3, const float* __restrict__ b3,
            float* __restrict__ out) {
    extern __shared__ float hs[];
    float* za = hs;               // 64 x 128
    float* zb = hs + GG * HH;     // 64 x 128
    __shared__ float sc_s[HH], sh_s[HH];
    int t = threadIdx.x;
    int gq = t >> 7;              // 0..7
    int c = t & 127;

    // mean pool finalize
    for (int g = gq; g < GG; g += 8) {
        float cnt = (float)g_pcnt[g];
        za[g * HH + c] = g_pooled[g * HH + c] / fmaxf(cnt, 1.f);
    }
    __syncthreads();

    // z1 = za @ W1 + b1
    for (int g = gq; g < GG; g += 8) {
        float acc = b1[c];
#pragma unroll 4
        for (int k = 0; k < HH; k++) acc += za[g * HH + k] * W1[k * HH + c];
        zb[g * HH + c] = acc;
    }
    __syncthreads();

    // BN over graphs
    if (t < HH) {
        float s = 0.f, s2 = 0.f;
        for (int g = 0; g < GG; g++) { float v = zb[g * HH + t]; s += v; s2 += v * v; }
        float mu = s / (float)GG;
        float var = s2 / (float)GG - mu * mu;
        float scv = rsqrtf(var + EPS) * bng[t];
        sc_s[t] = scv;
        sh_s[t] = bnb[t] - mu * scv;
    }
    __syncthreads();
    for (int g = gq; g < GG; g += 8)
        zb[g * HH + c] = fmaxf(zb[g * HH + c] * sc_s[c] + sh_s[c], 0.f);
    __syncthreads();

    // z2 = relu(zb @ W2 + b2)
    for (int g = gq; g < GG; g += 8) {
        float acc = b2[c];
#pragma unroll 4
        for (int k = 0; k < HH; k++) acc += zb[g * HH + k] * W2[k * HH + c];
        za[g * HH + c] = fmaxf(acc, 0.f);
    }
    __syncthreads();

    // out = za @ W3 + b3
    int g3 = t >> 4, o = t & 15;
    if (o < OUTC) {
        float acc = b3[o];
#pragma unroll 4
        for (int k = 0; k < HH; k++) acc += za[g3 * HH + k] * W3[k * OUTC + o];
        out[g3 * OUTC + o] = acc;
    }
}

// ---------------- launch ----------------------------------------------------
extern "C" void kernel_launch(void* const* d_in, const int* in_sizes, int n_in,
                              void* d_out, int out_size) {
    const float* x        = (const float*)d_in[0];
    const int*   eidx     = (const int*)  d_in[1];
    const int*   batch    = (const int*)  d_in[2];
    const float* conv_W   = (const float*)d_in[3];
    const float* conv_b   = (const float*)d_in[4];
    const float* bn_gamma = (const float*)d_in[5];
    const float* bn_beta  = (const float*)d_in[6];
    const float* head_W1  = (const float*)d_in[7];
    const float* head_b1  = (const float*)d_in[8];
    const float* head_bng = (const float*)d_in[9];
    const float* head_bnb = (const float*)d_in[10];
    const float* head_W2  = (const float*)d_in[11];
    const float* head_b2  = (const float*)d_in[12];
    const float* head_W3  = (const float*)d_in[13];
    const float* head_b3  = (const float*)d_in[14];
    float* out = (float*)d_out;

    const int* src = eidx;
    const int* dst = eidx + EE;

    float *buf, *lin, *stats;
    cudaGetSymbolAddress((void**)&buf,   g_buf);
    cudaGetSymbolAddress((void**)&lin,   g_lin);
    cudaGetSymbolAddress((void**)&stats, g_stats);

    cudaFuncSetAttribute(k_gemm, cudaFuncAttributeMaxDynamicSharedMemorySize, SMEM_TC);
    cudaFuncSetAttribute(k_head, cudaFuncAttributeMaxDynamicSharedMemorySize, HEAD_SMEM);

    // one side stream + fork/join events (created once; host-side only)
    static cudaStream_t s2 = nullptr;
    static cudaEvent_t evRoot = nullptr, evJoin = nullptr;
    if (!s2) {
        cudaStreamCreateWithFlags(&s2, cudaStreamNonBlocking);
        cudaEventCreateWithFlags(&evRoot, cudaEventDisableTiming);
        cudaEventCreateWithFlags(&evJoin, cudaEventDisableTiming);
    }

    // --- fork: graph preprocessing on s2, GEMM L0 on main (independent) ---
    cudaEventRecord(evRoot, 0);
    cudaStreamWaitEvent(s2, evRoot, 0);

    k_zero_counts<<<(NN + 511) / 512, 512, 0, s2>>>();            // launch 1
    k_hist<<<(EE / 4 + 255) / 256, 256, 0, s2>>>(dst);            // launch 2
    k_scan_local<<<NPART, 512, 0, s2>>>();                        // launch 3
    k_gemm<<<GEMM_GRID, 256, SMEM_TC>>>(x, conv_W, lin,           // launch 4 (profiled)
                                        nullptr, nullptr, nullptr, 0);
    k_scan_part<<<1, 128, 0, s2>>>();                             // launch 5
    k_scan_add<<<(NN + 511) / 512, 512, 0, s2>>>();               // launch 6
    k_dinv<<<(NN + 255) / 256, 256, 0, s2>>>();                   // launch 7
    k_scatter<<<(EE + 255) / 256, 256, 0, s2>>>(src, dst);        // launch 8

    cudaEventRecord(evJoin, s2);
    cudaStreamWaitEvent(0, evJoin, 0);

    // --- GCN layers (L0 GEMM already issued above) ---
    k_agg<<<1024, 256>>>(lin, conv_b, buf, stats, 1);
    for (int l = 1; l < LL; l++) {
        const float* st_in = stats + (l - 1) * 2 * HH;
        const float* ga = bn_gamma + (l - 1) * HH;
        const float* be = bn_beta + (l - 1) * HH;
        k_gemm<<<GEMM_GRID, 256, SMEM_TC>>>(buf, conv_W + l * HH * HH, lin,
                                            st_in, ga, be, 1);
        float* st_out = (l < LL - 1) ? stats + l * 2 * HH : nullptr;
        k_agg<<<1024, 256>>>(lin, conv_b + l * HH, buf, st_out, l < LL - 1 ? 1 : 0);
    }

    // --- pool + fused head ---
    k_pool<<<dim3(GG, 4), HH>>>(buf, batch);
    k_head<<<1, 1024, HEAD_SMEM>>>(head_W1, head_b1, head_bng, head_bnb,
                                   head_W2, head_b2, head_W3, head_b3, out);
}

// round 14
// speedup vs baseline: 1.1690x; 1.1690x over previous
#include <cuda_runtime.h>
#include <cuda_bf16.h>
#include <math.h>
#include <cstdint>

#define NN   50000
#define EE   800000
#define HH   128
#define GG   64
#define LL   6
#define OUTC 10
#define EPS  1e-5f
#define NPART 98            // ceil(NN/512)
#define TM   32
#define TILES32 ((NN + TM - 1) / TM)
#define GEMM_GRID 148       // 1 CTA/SM persistent
#define BP   136            // bf16 smem pitch (272B rows)

typedef unsigned long long ull;

// ---------------- scratch (device globals) ----------------------------------
__device__ float g_buf [NN * HH];
__device__ float g_lin [NN * HH];
__device__ int   g_cnt [NN];
__device__ int   g_cur [NN];
__device__ int   g_rowptr[NN + 1];
__device__ int   g_part[NPART];
__device__ int   g_col [EE];
__device__ float g_wgt [EE];
__device__ float g_dinv[NN];
__device__ float g_selfw[NN];
__device__ float g_stats[(LL - 1) * 2 * HH];
__device__ float g_pooled[GG * HH];
__device__ float g_z1[GG * HH];
__device__ float g_z2[GG * HH];

// ---------------- mma / ldmatrix helpers -------------------------------------
__device__ __forceinline__ uint32_t smem_u32(const void* p) {
    uint32_t a;
    asm("{ .reg .u64 t; cvta.to.shared.u64 t, %1; cvt.u32.u64 %0, t; }" : "=r"(a) : "l"(p));
    return a;
}
__device__ __forceinline__ void ldmx4(uint32_t& r0, uint32_t& r1, uint32_t& r2,
                                      uint32_t& r3, uint32_t a) {
    asm volatile("ldmatrix.sync.aligned.m8n8.x4.shared.b16 {%0,%1,%2,%3}, [%4];"
                 : "=r"(r0), "=r"(r1), "=r"(r2), "=r"(r3) : "r"(a));
}
__device__ __forceinline__ void mma_bf16(float* c, const uint32_t* a,
                                         uint32_t b0, uint32_t b1) {
    asm volatile("mma.sync.aligned.m16n8k16.row.col.f32.bf16.bf16.f32 "
                 "{%0,%1,%2,%3}, {%4,%5,%6,%7}, {%8,%9}, {%0,%1,%2,%3};"
                 : "+f"(c[0]), "+f"(c[1]), "+f"(c[2]), "+f"(c[3])
                 : "r"(a[0]), "r"(a[1]), "r"(a[2]), "r"(a[3]), "r"(b0), "r"(b1));
}
__device__ __forceinline__ uint32_t pack_hi(float x, float y) {
    __nv_bfloat162 h(__float2bfloat16_rn(x), __float2bfloat16_rn(y));
    return *(uint32_t*)&h;
}
__device__ __forceinline__ uint32_t pack_lo(float x, float y) {
    __nv_bfloat16 hx = __float2bfloat16_rn(x);
    __nv_bfloat16 hy = __float2bfloat16_rn(y);
    __nv_bfloat162 l(__float2bfloat16_rn(x - __bfloat162float(hx)),
                     __float2bfloat16_rn(y - __bfloat162float(hy)));
    return *(uint32_t*)&l;
}

// ---------------- graph preprocessing ---------------------------------------
__global__ void k_zero_counts() {
    int i = blockIdx.x * blockDim.x + threadIdx.x;
    if (i < NN) { g_cnt[i] = 0; g_cur[i] = 0; }
    if (i < (LL - 1) * 2 * HH) g_stats[i] = 0.f;
}

__global__ void k_hist(const int* __restrict__ dst) {
    int i = blockIdx.x * blockDim.x + threadIdx.x;
    if (i < EE / 4) {
        int4 d = ((const int4*)dst)[i];
        atomicAdd(&g_cnt[d.x], 1);
        atomicAdd(&g_cnt[d.y], 1);
        atomicAdd(&g_cnt[d.z], 1);
        atomicAdd(&g_cnt[d.w], 1);
    }
}

__global__ void k_scan_local() {
    __shared__ int wsum[16];
    int t = threadIdx.x;                 // 512
    int i = blockIdx.x * 512 + t;
    int v = (i < NN) ? g_cnt[i] : 0;
    int lane = t & 31, w = t >> 5;
    int x = v;
#pragma unroll
    for (int off = 1; off < 32; off <<= 1) {
        int y = __shfl_up_sync(0xffffffff, x, off);
        if (lane >= off) x += y;
    }
    if (lane == 31) wsum[w] = x;
    __syncthreads();
    if (w == 0) {
        int s = (lane < 16) ? wsum[lane] : 0;
#pragma unroll
        for (int off = 1; off < 16; off <<= 1) {
            int y = __shfl_up_sync(0xffffffff, s, off);
            if (lane >= off) s += y;
        }
        if (lane < 16) wsum[lane] = s;
    }
    __syncthreads();
    int incl = x + (w > 0 ? wsum[w - 1] : 0);
    if (i < NN) g_rowptr[i + 1] = incl;
    if (t == 511) g_part[blockIdx.x] = incl;
}

__global__ void k_scan_part() {
    __shared__ int wsum[4];
    int t = threadIdx.x;                 // 128
    int lane = t & 31, w = t >> 5;
    int v = (t < NPART) ? g_part[t] : 0;
    int x = v;
#pragma unroll
    for (int off = 1; off < 32; off <<= 1) {
        int y = __shfl_up_sync(0xffffffff, x, off);
        if (lane >= off) x += y;
    }
    if (lane == 31) wsum[w] = x;
    __syncthreads();
    if (w == 0 && lane < 4) {
        int s = wsum[lane];
#pragma unroll
        for (int off = 1; off < 4; off <<= 1) {
            int y = __shfl_up_sync(0x0000000f, s, off);
            if (lane >= off) s += y;
        }
        wsum[lane] = s;
    }
    __syncthreads();
    int incl = x + (w > 0 ? wsum[w - 1] : 0);
    if (t < NPART) g_part[t] = incl - v;   // exclusive
}

__global__ void k_scan_add() {
    int i = blockIdx.x * blockDim.x + threadIdx.x;
    if (i < NN) g_rowptr[i + 1] += g_part[i >> 9];
    if (i == 0) g_rowptr[0] = 0;
}

__global__ void k_dinv() {
    int i = blockIdx.x * blockDim.x + threadIdx.x;
    if (i < NN) {
        float deg = (float)(g_cnt[i] + 1);
        g_dinv[i] = rsqrtf(deg);
        g_selfw[i] = 1.f / deg;
    }
}

__global__ void k_scatter(const int* __restrict__ src, const int* __restrict__ dst) {
    int i = blockIdx.x * blockDim.x + threadIdx.x;
    if (i < EE) {
        int s = src[i], d = dst[i];
        int p = atomicAdd(&g_cur[d], 1);
        int idx = g_rowptr[d] + p;
        g_col[idx] = s;
        g_wgt[idx] = g_dinv[s] * g_dinv[d];
    }
}

// ---------------- tensor-core GEMM: Y = act(X) @ W ---------------------------
// mma.sync m16n8k16 bf16, 3-pass split. 32-row tiles (4% tail imbalance).
// Warp = 16 rows x 32 cols; B fragments register-resident for the CTA
// lifetime; next tile's X rows prefetched into registers.
#define SM_BHI  0
#define SM_BLO  (SM_BHI + HH * BP * 2)
#define SM_XHI  (SM_BLO + HH * BP * 2)
#define SM_XLO  (SM_XHI + TM * BP * 2)
#define SM_SC   (SM_XLO + TM * BP * 2)
#define SM_SH   (SM_SC + 512)
#define SMEM_TC (SM_SH + 512)

__global__ __launch_bounds__(256, 1)
void k_gemm(const float* __restrict__ X, const float* __restrict__ W,
            float* __restrict__ Y,
            const float* __restrict__ stats,
            const float* __restrict__ gamma, const float* __restrict__ beta,
            int bn) {
    extern __shared__ char smem[];
    __nv_bfloat16* Bh = (__nv_bfloat16*)(smem + SM_BHI);
    __nv_bfloat16* Bl = (__nv_bfloat16*)(smem + SM_BLO);
    float* sc = (float*)(smem + SM_SC);
    float* shf = (float*)(smem + SM_SH);

    int tid = threadIdx.x;
    int lr = tid >> 3;                    // fill row 0..31
    int kq0 = tid & 7;                    // fill float4 phase

    // ---- prefetch first tile into registers ----
    float4 pf[4];
    {
        int grow = blockIdx.x * TM + lr;
        bool rv = grow < NN;
        const float4* Xg = (const float4*)(X + (size_t)(rv ? grow : 0) * HH);
#pragma unroll
        for (int i = 0; i < 4; i++)
            pf[i] = rv ? Xg[kq0 + i * 8] : make_float4(0.f, 0.f, 0.f, 0.f);
    }

    if (bn && tid < HH) {
        float mu  = stats[tid] * (1.f / NN);
        float var = stats[HH + tid] * (1.f / NN) - mu * mu;
        float s = rsqrtf(var + EPS) * gamma[tid];
        sc[tid] = s;
        shf[tid] = beta[tid] - mu * s;
    }

    {   // split W into Bt[n][k] hi/lo (once per CTA)
        const float4* W4 = (const float4*)W;
        for (int i = tid; i < HH * 32; i += 256) {
            int k = i >> 5, n4 = i & 31;
            float4 v = W4[k * 32 + n4];
            const float* vv = (const float*)&v;
#pragma unroll
            for (int j = 0; j < 4; j++) {
                int n = n4 * 4 + j;
                __nv_bfloat16 hi = __float2bfloat16_rn(vv[j]);
                Bh[n * BP + k] = hi;
                Bl[n * BP + k] = __float2bfloat16_rn(vv[j] - __bfloat162float(hi));
            }
        }
    }
    __syncthreads();

    uint32_t xh_u = smem_u32(smem + SM_XHI);
    uint32_t xl_u = smem_u32(smem + SM_XLO);
    uint32_t bh_u = smem_u32(smem + SM_BHI);
    uint32_t bl_u = smem_u32(smem + SM_BLO);

    int warp = tid >> 5, lane = tid & 31;
    int mrow = (warp & 1) * 16;           // 2 row groups of 16
    int ncol = (warp >> 1) * 32;          // 4 col groups of 32

    int aj = lane >> 3, ar = lane & 7;
    int a_rb  = ((aj & 1) << 3) + ar;
    int a_kad = (aj >> 1) << 3;
    int b_rowoff = ((aj >> 1) << 3) + ar;
    int b_kad = (aj & 1) << 3;

    // ---- preload ALL B fragments for this warp's 32 cols ----
    uint32_t bhr[8][2][4], blr[8][2][4];
#pragma unroll
    for (int ks = 0; ks < 8; ks++)
#pragma unroll
        for (int ng = 0; ng < 2; ng++) {
            int n0 = ncol + 16 * ng;
            uint32_t boff = (uint32_t)(((n0 + b_rowoff) * BP + ks * 16 + b_kad) * 2);
            ldmx4(bhr[ks][ng][0], bhr[ks][ng][1], bhr[ks][ng][2], bhr[ks][ng][3], bh_u + boff);
            ldmx4(blr[ks][ng][0], blr[ks][ng][1], blr[ks][ng][2], blr[ks][ng][3], bl_u + boff);
        }

    for (int tile = blockIdx.x; tile < TILES32; tile += gridDim.x) {
        int row0 = tile * TM;

        {   // fill X hi/lo tiles from prefetched registers (BN/ReLU fused)
#pragma unroll
            for (int i = 0; i < 4; i++) {
                int m = kq0 + i * 8;
                float4 v = pf[i];
                if (bn) {
                    int ch = 4 * m;
                    v.x = fmaxf(v.x * sc[ch]     + shf[ch],     0.f);
                    v.y = fmaxf(v.y * sc[ch + 1] + shf[ch + 1], 0.f);
                    v.z = fmaxf(v.z * sc[ch + 2] + shf[ch + 2], 0.f);
                    v.w = fmaxf(v.w * sc[ch + 3] + shf[ch + 3], 0.f);
                }
                uint2 hp, lp;
                hp.x = pack_hi(v.x, v.y); hp.y = pack_hi(v.z, v.w);
                lp.x = pack_lo(v.x, v.y); lp.y = pack_lo(v.z, v.w);
                *(uint2*)(smem + SM_XHI + (lr * BP + 4 * m) * 2) = hp;
                *(uint2*)(smem + SM_XLO + (lr * BP + 4 * m) * 2) = lp;
            }
        }

        {   // prefetch next tile's rows (hidden behind the mma)
            int ntile = tile + gridDim.x;
            if (ntile < TILES32) {
                int grow = ntile * TM + lr;
                bool rv = grow < NN;
                const float4* Xg = (const float4*)(X + (size_t)(rv ? grow : 0) * HH);
#pragma unroll
                for (int i = 0; i < 4; i++)
                    pf[i] = rv ? Xg[kq0 + i * 8] : make_float4(0.f, 0.f, 0.f, 0.f);
            }
        }
        __syncthreads();

        float c[2][2][4];
#pragma unroll
        for (int ng = 0; ng < 2; ng++)
#pragma unroll
            for (int nh = 0; nh < 2; nh++)
#pragma unroll
                for (int j = 0; j < 4; j++) c[ng][nh][j] = 0.f;

#pragma unroll
        for (int ks = 0; ks < 8; ks++) {
            int k0 = ks * 16;
            uint32_t ahi[4], alo[4];
            uint32_t aoff = (uint32_t)(((mrow + a_rb) * BP + k0 + a_kad) * 2);
            ldmx4(ahi[0], ahi[1], ahi[2], ahi[3], xh_u + aoff);
            ldmx4(alo[0], alo[1], alo[2], alo[3], xl_u + aoff);
#pragma unroll
            for (int ng = 0; ng < 2; ng++) {
                const uint32_t* bh = bhr[ks][ng];
                const uint32_t* bl = blr[ks][ng];
                mma_bf16(c[ng][0], ahi, bh[0], bh[1]);
                mma_bf16(c[ng][0], alo, bh[0], bh[1]);
                mma_bf16(c[ng][0], ahi, bl[0], bl[1]);
                mma_bf16(c[ng][1], ahi, bh[2], bh[3]);
                mma_bf16(c[ng][1], alo, bh[2], bh[3]);
                mma_bf16(c[ng][1], ahi, bl[2], bl[3]);
            }
        }

        {   // epilogue: c -> Y (fp32)
            int cb = 2 * (lane & 3);
            int rowin = lane >> 2;
            int m1 = row0 + mrow + rowin;
            int m2 = m1 + 8;
            bool v1 = m1 < NN, v2 = m2 < NN;
#pragma unroll
            for (int ng = 0; ng < 2; ng++)
#pragma unroll
                for (int nh = 0; nh < 2; nh++) {
                    int n0 = ncol + 16 * ng + 8 * nh + cb;
                    float* cc = c[ng][nh];
                    if (v1) *(float2*)(Y + (size_t)m1 * HH + n0) = make_float2(cc[0], cc[1]);
                    if (v2) *(float2*)(Y + (size_t)m2 * HH + n0) = make_float2(cc[2], cc[3]);
                }
        }
        __syncthreads();   // X tile reuse barrier
    }
}

// ---------------- aggregation (fp32 gather) + fused BN stats -----------------
__global__ __launch_bounds__(256)
void k_agg(const float* __restrict__ hlin, const float* __restrict__ bias,
           float* __restrict__ hout, float* __restrict__ stats, int do_stats) {
    int lane = threadIdx.x & 31;
    int warp = threadIdx.x >> 5;
    int gw = blockIdx.x * 8 + warp;
    int nw = gridDim.x * 8;

    const float4* h4 = (const float4*)hlin;
    float4 b4 = ((const float4*)bias)[lane];

    float4 s1 = make_float4(0.f, 0.f, 0.f, 0.f);
    float4 s2 = make_float4(0.f, 0.f, 0.f, 0.f);

    for (int n = gw; n < NN; n += nw) {
        int beg = g_rowptr[n], end = g_rowptr[n + 1];
        float4 acc = make_float4(0.f, 0.f, 0.f, 0.f);
        int e = beg;
        while (e < end) {
            int m2 = end - e; if (m2 > 8) m2 = 8;
            int   cc[8];
            float ww[8];
#pragma unroll
            for (int j = 0; j < 8; j++)
                if (j < m2) { cc[j] = g_col[e + j]; ww[j] = g_wgt[e + j]; }
#pragma unroll
            for (int j = 0; j < 8; j++)
                if (j < m2) {
                    float4 v = h4[(size_t)cc[j] * 32 + lane];
                    float w = ww[j];
                    acc.x += v.x * w; acc.y += v.y * w;
                    acc.z += v.z * w; acc.w += v.w * w;
                }
            e += m2;
        }
        float sw = g_selfw[n];
        float4 sf = h4[(size_t)n * 32 + lane];
        float4 o;
        o.x = acc.x + sf.x * sw + b4.x;
        o.y = acc.y + sf.y * sw + b4.y;
        o.z = acc.z + sf.z * sw + b4.z;
        o.w = acc.w + sf.w * sw + b4.w;
        ((float4*)hout)[(size_t)n * 32 + lane] = o;
        if (do_stats) {
            s1.x += o.x; s1.y += o.y; s1.z += o.z; s1.w += o.w;
            s2.x += o.x * o.x; s2.y += o.y * o.y;
            s2.z += o.z * o.z; s2.w += o.w * o.w;
        }
    }

    if (do_stats) {
        __shared__ float red[8][2 * HH];
        float* r = red[warp];
        int c = lane * 4;
        r[c] = s1.x; r[c + 1] = s1.y; r[c + 2] = s1.z; r[c + 3] = s1.w;
        r[HH + c] = s2.x; r[HH + c + 1] = s2.y;
        r[HH + c + 2] = s2.z; r[HH + c + 3] = s2.w;
        __syncthreads();
        int t = threadIdx.x;
        float s = 0.f;
#pragma unroll
        for (int w2 = 0; w2 < 8; w2++) s += red[w2][t];
        atomicAdd(&stats[t], s);
    }
}

// ---------------- global mean pool (batch sorted) ---------------------------
__device__ __forceinline__ int lowerb(const int* a, int n, int key) {
    int lo = 0, hi = n;
    while (lo < hi) {
        int m = (lo + hi) >> 1;
        if (a[m] < key) lo = m + 1; else hi = m;
    }
    return lo;
}

__global__ void k_pool(const float* __restrict__ h, const int* __restrict__ batch) {
    __shared__ float red[4][HH];
    int g = blockIdx.x;
    int c = threadIdx.x & 127;
    int sub = threadIdx.x >> 7;
    int lo = lowerb(batch, NN, g);
    int hi = lowerb(batch, NN, g + 1);
    float s = 0.f;
    for (int i = lo + sub; i < hi; i += 4) s += h[(size_t)i * HH + c];
    red[sub][c] = s;
    __syncthreads();
    if (sub == 0) {
        float tot = red[0][c] + red[1][c] + red[2][c] + red[3][c];
        int cnt = hi - lo;
        g_pooled[g * HH + c] = tot / (float)(cnt > 0 ? cnt : 1);
    }
}

// ---------------- prediction head -------------------------------------------
__global__ void k_head_gemm(const float* __restrict__ X, const float* __restrict__ W,
                            const float* __restrict__ b, float* __restrict__ Y,
                            int relu) {
    __shared__ float xs[HH];
    int g = blockIdx.x, c = threadIdx.x;
    xs[c] = X[g * HH + c];
    __syncthreads();
    float acc = b[c];
#pragma unroll
    for (int k = 0; k < HH; k++) acc += xs[k] * W[k * HH + c];
    if (relu) acc = fmaxf(acc, 0.f);
    Y[g * HH + c] = acc;
}

__global__ void k_headbn(const float* __restrict__ gamma, const float* __restrict__ beta) {
    int c = threadIdx.x;
    float s = 0.f, s2 = 0.f;
    for (int g = 0; g < GG; g++) {
        float v = g_z1[g * HH + c];
        s += v; s2 += v * v;
    }
    float mu = s / (float)GG;
    float var = s2 / (float)GG - mu * mu;
    float sc = rsqrtf(var + EPS) * gamma[c];
    float sh = beta[c] - mu * sc;
    for (int g = 0; g < GG; g++) {
        float v = g_z1[g * HH + c] * sc + sh;
        g_z1[g * HH + c] = fmaxf(v, 0.f);
    }
}

__global__ void k_head_out(const float* __restrict__ X, const float* __restrict__ W,
                           const float* __restrict__ b, float* __restrict__ Y) {
    __shared__ float xs[HH];
    int g = blockIdx.x, t = threadIdx.x;
    for (int i = t; i < HH; i += 32) xs[i] = X[g * HH + i];
    __syncthreads();
    if (t < OUTC) {
        float acc = b[t];
#pragma unroll
        for (int k = 0; k < HH; k++) acc += xs[k] * W[k * OUTC + t];
        Y[g * OUTC + t] = acc;
    }
}

// ---------------- launch ----------------------------------------------------
extern "C" void kernel_launch(void* const* d_in, const int* in_sizes, int n_in,
                              void* d_out, int out_size) {
    const float* x        = (const float*)d_in[0];
    const int*   eidx     = (const int*)  d_in[1];
    const int*   batch    = (const int*)  d_in[2];
    const float* conv_W   = (const float*)d_in[3];
    const float* conv_b   = (const float*)d_in[4];
    const float* bn_gamma = (const float*)d_in[5];
    const float* bn_beta  = (const float*)d_in[6];
    const float* head_W1  = (const float*)d_in[7];
    const float* head_b1  = (const float*)d_in[8];
    const float* head_bng = (const float*)d_in[9];
    const float* head_bnb = (const float*)d_in[10];
    const float* head_W2  = (const float*)d_in[11];
    const float* head_b2  = (const float*)d_in[12];
    const float* head_W3  = (const float*)d_in[13];
    const float* head_b3  = (const float*)d_in[14];
    float* out = (float*)d_out;

    const int* src = eidx;
    const int* dst = eidx + EE;

    float *buf, *lin, *pooled, *z1, *z2, *stats;
    cudaGetSymbolAddress((void**)&buf,    g_buf);
    cudaGetSymbolAddress((void**)&lin,    g_lin);
    cudaGetSymbolAddress((void**)&pooled, g_pooled);
    cudaGetSymbolAddress((void**)&z1,     g_z1);
    cudaGetSymbolAddress((void**)&z2,     g_z2);
    cudaGetSymbolAddress((void**)&stats,  g_stats);

    cudaFuncSetAttribute(k_gemm, cudaFuncAttributeMaxDynamicSharedMemorySize, SMEM_TC);

    // one side stream + fork/join events (created once; host-side only)
    static cudaStream_t s2 = nullptr;
    static cudaEvent_t evRoot = nullptr, evJoin = nullptr;
    if (!s2) {
        cudaStreamCreateWithFlags(&s2, cudaStreamNonBlocking);
        cudaEventCreateWithFlags(&evRoot, cudaEventDisableTiming);
        cudaEventCreateWithFlags(&evJoin, cudaEventDisableTiming);
    }

    // --- fork: graph preprocessing on s2, GEMM L0 on main (independent) ---
    cudaEventRecord(evRoot, 0);
    cudaStreamWaitEvent(s2, evRoot, 0);

    k_zero_counts<<<(NN + 511) / 512, 512, 0, s2>>>();            // launch 1
    k_hist<<<(EE / 4 + 255) / 256, 256, 0, s2>>>(dst);            // launch 2
    k_scan_local<<<NPART, 512, 0, s2>>>();                        // launch 3
    k_gemm<<<GEMM_GRID, 256, SMEM_TC>>>(x, conv_W, lin,           // launch 4 (profiled)
                                        nullptr, nullptr, nullptr, 0);
    k_scan_part<<<1, 128, 0, s2>>>();                             // launch 5
    k_scan_add<<<(NN + 511) / 512, 512, 0, s2>>>();               // launch 6
    k_dinv<<<(NN + 255) / 256, 256, 0, s2>>>();                   // launch 7
    k_scatter<<<(EE + 255) / 256, 256, 0, s2>>>(src, dst);        // launch 8

    cudaEventRecord(evJoin, s2);
    cudaStreamWaitEvent(0, evJoin, 0);

    // --- GCN layers (L0 GEMM already issued above) ---
    k_agg<<<1024, 256>>>(lin, conv_b, buf, stats, 1);
    for (int l = 1; l < LL; l++) {
        const float* st_in = stats + (l - 1) * 2 * HH;
        const float* ga = bn_gamma + (l - 1) * HH;
        const float* be = bn_beta + (l - 1) * HH;
        k_gemm<<<GEMM_GRID, 256, SMEM_TC>>>(buf, conv_W + l * HH * HH, lin,
                                            st_in, ga, be, 1);
        float* st_out = (l < LL - 1) ? stats + l * 2 * HH : nullptr;
        k_agg<<<1024, 256>>>(lin, conv_b + l * HH, buf, st_out, l < LL - 1 ? 1 : 0);
    }

    // --- pool + head ---
    k_pool<<<GG, 512>>>(buf, batch);
    k_head_gemm<<<GG, HH>>>(pooled, head_W1, head_b1, z1, 0);
    k_headbn<<<1, HH>>>(head_bng, head_bnb);
    k_head_gemm<<<GG, HH>>>(z1, head_W2, head_b2, z2, 1);
    k_head_out<<<GG, 32>>>(z2, head_W3, head_b3, out);
}

// round 15
// speedup vs baseline: 1.2255x; 1.0483x over previous
#include <cuda_runtime.h>
#include <cuda_bf16.h>
#include <math.h>
#include <cstdint>

#define NN   50000
#define EE   800000
#define HH   128
#define GG   64
#define LL   6
#define OUTC 10
#define EPS  1e-5f
#define NPART 98            // ceil(NN/512)
#define TM   32
#define TILES32 ((NN + TM - 1) / TM)
#define GEMM_GRID 148       // 1 CTA/SM persistent
#define BP   136            // bf16 smem pitch (272B rows)

typedef unsigned long long ull;

// ---------------- scratch (device globals) ----------------------------------
__device__ float g_buf [NN * HH];
__device__ float g_lin [NN * HH];
__device__ int   g_cnt [NN];
__device__ int   g_cur [NN];
__device__ int   g_rowptr[NN + 1];
__device__ int   g_part[NPART];
__device__ int2  g_cw  [EE];          // interleaved (col, wgt-bits)
__device__ float g_dinv[NN];
__device__ float g_selfw[NN];
__device__ float g_stats[(LL - 1) * 2 * HH];
__device__ float g_pooled[GG * HH];
__device__ float g_z1[GG * HH];
__device__ float g_z2[GG * HH];

// ---------------- mma / ldmatrix helpers -------------------------------------
__device__ __forceinline__ uint32_t smem_u32(const void* p) {
    uint32_t a;
    asm("{ .reg .u64 t; cvta.to.shared.u64 t, %1; cvt.u32.u64 %0, t; }" : "=r"(a) : "l"(p));
    return a;
}
__device__ __forceinline__ void ldmx4(uint32_t& r0, uint32_t& r1, uint32_t& r2,
                                      uint32_t& r3, uint32_t a) {
    asm volatile("ldmatrix.sync.aligned.m8n8.x4.shared.b16 {%0,%1,%2,%3}, [%4];"
                 : "=r"(r0), "=r"(r1), "=r"(r2), "=r"(r3) : "r"(a));
}
__device__ __forceinline__ void mma_bf16(float* c, const uint32_t* a,
                                         uint32_t b0, uint32_t b1) {
    asm volatile("mma.sync.aligned.m16n8k16.row.col.f32.bf16.bf16.f32 "
                 "{%0,%1,%2,%3}, {%4,%5,%6,%7}, {%8,%9}, {%0,%1,%2,%3};"
                 : "+f"(c[0]), "+f"(c[1]), "+f"(c[2]), "+f"(c[3])
                 : "r"(a[0]), "r"(a[1]), "r"(a[2]), "r"(a[3]), "r"(b0), "r"(b1));
}
// truncation split: hi = top16 bits (PRMT pair), lo = rn_bf16(v - hi) (packed cvt)
__device__ __forceinline__ void pack_pair(float x, float y, uint32_t& hp, uint32_t& lp) {
    uint32_t ux = __float_as_uint(x), uy = __float_as_uint(y);
    hp = __byte_perm(ux, uy, 0x7632);
    float lx = x - __uint_as_float(ux & 0xFFFF0000u);
    float ly = y - __uint_as_float(uy & 0xFFFF0000u);
    asm("cvt.rn.bf16x2.f32 %0, %1, %2;" : "=r"(lp) : "f"(ly), "f"(lx));
}

// ---------------- graph preprocessing ---------------------------------------
__global__ void k_zero_counts() {
    int i = blockIdx.x * blockDim.x + threadIdx.x;
    if (i < NN) { g_cnt[i] = 0; g_cur[i] = 0; }
    if (i < (LL - 1) * 2 * HH) g_stats[i] = 0.f;
}

__global__ void k_hist(const int* __restrict__ dst) {
    int i = blockIdx.x * blockDim.x + threadIdx.x;
    if (i < EE / 4) {
        int4 d = ((const int4*)dst)[i];
        atomicAdd(&g_cnt[d.x], 1);
        atomicAdd(&g_cnt[d.y], 1);
        atomicAdd(&g_cnt[d.z], 1);
        atomicAdd(&g_cnt[d.w], 1);
    }
}

__global__ void k_scan_local() {
    __shared__ int wsum[16];
    int t = threadIdx.x;                 // 512
    int i = blockIdx.x * 512 + t;
    int v = (i < NN) ? g_cnt[i] : 0;
    int lane = t & 31, w = t >> 5;
    int x = v;
#pragma unroll
    for (int off = 1; off < 32; off <<= 1) {
        int y = __shfl_up_sync(0xffffffff, x, off);
        if (lane >= off) x += y;
    }
    if (lane == 31) wsum[w] = x;
    __syncthreads();
    if (w == 0) {
        int s = (lane < 16) ? wsum[lane] : 0;
#pragma unroll
        for (int off = 1; off < 16; off <<= 1) {
            int y = __shfl_up_sync(0xffffffff, s, off);
            if (lane >= off) s += y;
        }
        if (lane < 16) wsum[lane] = s;
    }
    __syncthreads();
    int incl = x + (w > 0 ? wsum[w - 1] : 0);
    if (i < NN) g_rowptr[i + 1] = incl;
    if (t == 511) g_part[blockIdx.x] = incl;
}

__global__ void k_scan_part() {
    __shared__ int wsum[4];
    int t = threadIdx.x;                 // 128
    int lane = t & 31, w = t >> 5;
    int v = (t < NPART) ? g_part[t] : 0;
    int x = v;
#pragma unroll
    for (int off = 1; off < 32; off <<= 1) {
        int y = __shfl_up_sync(0xffffffff, x, off);
        if (lane >= off) x += y;
    }
    if (lane == 31) wsum[w] = x;
    __syncthreads();
    if (w == 0 && lane < 4) {
        int s = wsum[lane];
#pragma unroll
        for (int off = 1; off < 4; off <<= 1) {
            int y = __shfl_up_sync(0x0000000f, s, off);
            if (lane >= off) s += y;
        }
        wsum[lane] = s;
    }
    __syncthreads();
    int incl = x + (w > 0 ? wsum[w - 1] : 0);
    if (t < NPART) g_part[t] = incl - v;   // exclusive
}

__global__ void k_scan_add() {
    int i = blockIdx.x * blockDim.x + threadIdx.x;
    if (i < NN) g_rowptr[i + 1] += g_part[i >> 9];
    if (i == 0) g_rowptr[0] = 0;
}

__global__ void k_dinv() {
    int i = blockIdx.x * blockDim.x + threadIdx.x;
    if (i < NN) {
        float deg = (float)(g_cnt[i] + 1);
        g_dinv[i] = rsqrtf(deg);
        g_selfw[i] = 1.f / deg;
    }
}

__global__ void k_scatter(const int* __restrict__ src, const int* __restrict__ dst) {
    int i = blockIdx.x * blockDim.x + threadIdx.x;
    if (i < EE) {
        int s = src[i], d = dst[i];
        int p = atomicAdd(&g_cur[d], 1);
        float w = g_dinv[s] * g_dinv[d];
        g_cw[g_rowptr[d] + p] = make_int2(s, __float_as_int(w));
    }
}

// ---------------- tensor-core GEMM: Y = act(X) @ W ---------------------------
// mma.sync m16n8k16 bf16, 3-pass truncation split. 32-row tiles; warp = 16
// rows x 32 cols; B fragments register-resident. X tiles DOUBLE-BUFFERED in
// smem: pack of tile t+1 overlaps mma of tile t, ONE barrier per tile.
#define SM_BHI  0
#define SM_BLO  (SM_BHI + HH * BP * 2)
#define SM_XHI0 (SM_BLO + HH * BP * 2)
#define SM_XLO0 (SM_XHI0 + TM * BP * 2)
#define SM_XHI1 (SM_XLO0 + TM * BP * 2)
#define SM_XLO1 (SM_XHI1 + TM * BP * 2)
#define SM_SC   (SM_XLO1 + TM * BP * 2)
#define SM_SH   (SM_SC + 512)
#define SMEM_TC (SM_SH + 512)

__global__ __launch_bounds__(256, 1)
void k_gemm(const float* __restrict__ X, const float* __restrict__ W,
            float* __restrict__ Y,
            const float* __restrict__ stats,
            const float* __restrict__ gamma, const float* __restrict__ beta,
            int bn) {
    extern __shared__ char smem[];
    __nv_bfloat16* Bh = (__nv_bfloat16*)(smem + SM_BHI);
    __nv_bfloat16* Bl = (__nv_bfloat16*)(smem + SM_BLO);
    float* sc = (float*)(smem + SM_SC);
    float* shf = (float*)(smem + SM_SH);

    int tid = threadIdx.x;
    int lr = tid >> 3;                    // fill row 0..31
    int kq0 = tid & 7;                    // fill float4 phase

    const uint32_t xhi_off[2] = { SM_XHI0, SM_XHI1 };
    const uint32_t xlo_off[2] = { SM_XLO0, SM_XLO1 };

    // ---- prefetch tile0 into registers ----
    float4 pf[4];
    {
        int grow = blockIdx.x * TM + lr;
        bool rv = grow < NN;
        const float4* Xg = (const float4*)(X + (size_t)(rv ? grow : 0) * HH);
#pragma unroll
        for (int i = 0; i < 4; i++)
            pf[i] = rv ? Xg[kq0 + i * 8] : make_float4(0.f, 0.f, 0.f, 0.f);
    }

    if (bn && tid < HH) {
        float mu  = stats[tid] * (1.f / NN);
        float var = stats[HH + tid] * (1.f / NN) - mu * mu;
        float s = rsqrtf(var + EPS) * gamma[tid];
        sc[tid] = s;
        shf[tid] = beta[tid] - mu * s;
    }

    {   // split W into Bt[n][k] hi/lo (once per CTA, rounding split)
        const float4* W4 = (const float4*)W;
        for (int i = tid; i < HH * 32; i += 256) {
            int k = i >> 5, n4 = i & 31;
            float4 v = W4[k * 32 + n4];
            const float* vv = (const float*)&v;
#pragma unroll
            for (int j = 0; j < 4; j++) {
                int n = n4 * 4 + j;
                __nv_bfloat16 hi = __float2bfloat16_rn(vv[j]);
                Bh[n * BP + k] = hi;
                Bl[n * BP + k] = __float2bfloat16_rn(vv[j] - __bfloat162float(hi));
            }
        }
    }
    __syncthreads();

    uint32_t bh_u = smem_u32(smem + SM_BHI);
    uint32_t bl_u = smem_u32(smem + SM_BLO);
    uint32_t smem_base = smem_u32(smem);

    int warp = tid >> 5, lane = tid & 31;
    int mrow = (warp & 1) * 16;
    int ncol = (warp >> 1) * 32;

    int aj = lane >> 3, ar = lane & 7;
    int a_rb  = ((aj & 1) << 3) + ar;
    int a_kad = (aj >> 1) << 3;
    int b_rowoff = ((aj >> 1) << 3) + ar;
    int b_kad = (aj & 1) << 3;

    // ---- preload ALL B fragments for this warp's 32 cols ----
    uint32_t bhr[8][2][4], blr[8][2][4];
#pragma unroll
    for (int ks = 0; ks < 8; ks++)
#pragma unroll
        for (int ng = 0; ng < 2; ng++) {
            int n0 = ncol + 16 * ng;
            uint32_t boff = (uint32_t)(((n0 + b_rowoff) * BP + ks * 16 + b_kad) * 2);
            ldmx4(bhr[ks][ng][0], bhr[ks][ng][1], bhr[ks][ng][2], bhr[ks][ng][3], bh_u + boff);
            ldmx4(blr[ks][ng][0], blr[ks][ng][1], blr[ks][ng][2], blr[ks][ng][3], bl_u + boff);
        }

    // ---- prologue: pack tile0 into buf0, prefetch tile1 ----
    {
#pragma unroll
        for (int i = 0; i < 4; i++) {
            int m = kq0 + i * 8;
            float4 v = pf[i];
            if (bn) {
                int ch = 4 * m;
                v.x = fmaxf(v.x * sc[ch]     + shf[ch],     0.f);
                v.y = fmaxf(v.y * sc[ch + 1] + shf[ch + 1], 0.f);
                v.z = fmaxf(v.z * sc[ch + 2] + shf[ch + 2], 0.f);
                v.w = fmaxf(v.w * sc[ch + 3] + shf[ch + 3], 0.f);
            }
            uint2 hp, lp;
            pack_pair(v.x, v.y, hp.x, lp.x);
            pack_pair(v.z, v.w, hp.y, lp.y);
            *(uint2*)(smem + SM_XHI0 + (lr * BP + 4 * m) * 2) = hp;
            *(uint2*)(smem + SM_XLO0 + (lr * BP + 4 * m) * 2) = lp;
        }
        int ntile = blockIdx.x + gridDim.x;
        if (ntile < TILES32) {
            int grow = ntile * TM + lr;
            bool rv = grow < NN;
            const float4* Xg = (const float4*)(X + (size_t)(rv ? grow : 0) * HH);
#pragma unroll
            for (int i = 0; i < 4; i++)
                pf[i] = rv ? Xg[kq0 + i * 8] : make_float4(0.f, 0.f, 0.f, 0.f);
        }
    }
    __syncthreads();

    int cur = 0;
    for (int tile = blockIdx.x; tile < TILES32; tile += gridDim.x, cur ^= 1) {
        int row0 = tile * TM;
        int t1 = tile + gridDim.x;
        int t2 = t1 + gridDim.x;

        if (t1 < TILES32) {   // pack tile t+1 into the other buffer (overlaps this mma)
#pragma unroll
            for (int i = 0; i < 4; i++) {
                int m = kq0 + i * 8;
                float4 v = pf[i];
                if (bn) {
                    int ch = 4 * m;
                    v.x = fmaxf(v.x * sc[ch]     + shf[ch],     0.f);
                    v.y = fmaxf(v.y * sc[ch + 1] + shf[ch + 1], 0.f);
                    v.z = fmaxf(v.z * sc[ch + 2] + shf[ch + 2], 0.f);
                    v.w = fmaxf(v.w * sc[ch + 3] + shf[ch + 3], 0.f);
                }
                uint2 hp, lp;
                pack_pair(v.x, v.y, hp.x, lp.x);
                pack_pair(v.z, v.w, hp.y, lp.y);
                *(uint2*)(smem + xhi_off[cur ^ 1] + (lr * BP + 4 * m) * 2) = hp;
                *(uint2*)(smem + xlo_off[cur ^ 1] + (lr * BP + 4 * m) * 2) = lp;
            }
        }
        if (t2 < TILES32) {   // prefetch tile t+2 rows into registers
            int grow = t2 * TM + lr;
            bool rv = grow < NN;
            const float4* Xg = (const float4*)(X + (size_t)(rv ? grow : 0) * HH);
#pragma unroll
            for (int i = 0; i < 4; i++)
                pf[i] = rv ? Xg[kq0 + i * 8] : make_float4(0.f, 0.f, 0.f, 0.f);
        }

        uint32_t xh_u = smem_base + xhi_off[cur];
        uint32_t xl_u = smem_base + xlo_off[cur];

        float c[2][2][4];
#pragma unroll
        for (int ng = 0; ng < 2; ng++)
#pragma unroll
            for (int nh = 0; nh < 2; nh++)
#pragma unroll
                for (int j = 0; j < 4; j++) c[ng][nh][j] = 0.f;

#pragma unroll
        for (int ks = 0; ks < 8; ks++) {
            int k0 = ks * 16;
            uint32_t ahi[4], alo[4];
            uint32_t aoff = (uint32_t)(((mrow + a_rb) * BP + k0 + a_kad) * 2);
            ldmx4(ahi[0], ahi[1], ahi[2], ahi[3], xh_u + aoff);
            ldmx4(alo[0], alo[1], alo[2], alo[3], xl_u + aoff);
#pragma unroll
            for (int ng = 0; ng < 2; ng++) {
                const uint32_t* bh = bhr[ks][ng];
                const uint32_t* bl = blr[ks][ng];
                mma_bf16(c[ng][0], ahi, bh[0], bh[1]);
                mma_bf16(c[ng][0], alo, bh[0], bh[1]);
                mma_bf16(c[ng][0], ahi, bl[0], bl[1]);
                mma_bf16(c[ng][1], ahi, bh[2], bh[3]);
                mma_bf16(c[ng][1], alo, bh[2], bh[3]);
                mma_bf16(c[ng][1], ahi, bl[2], bl[3]);
            }
        }

        {   // epilogue: c -> Y (fp32)
            int cb = 2 * (lane & 3);
            int rowin = lane >> 2;
            int m1 = row0 + mrow + rowin;
            int m2 = m1 + 8;
            bool v1 = m1 < NN, v2 = m2 < NN;
#pragma unroll
            for (int ng = 0; ng < 2; ng++)
#pragma unroll
                for (int nh = 0; nh < 2; nh++) {
                    int n0 = ncol + 16 * ng + 8 * nh + cb;
                    float* cc = c[ng][nh];
                    if (v1) *(float2*)(Y + (size_t)m1 * HH + n0) = make_float2(cc[0], cc[1]);
                    if (v2) *(float2*)(Y + (size_t)m2 * HH + n0) = make_float2(cc[2], cc[3]);
                }
        }
        __syncthreads();   // pack(t+1) visible; mma(t) done before pack(t+2) overwrites
    }
}

// ---------------- aggregation (fp32 gather) + fused BN stats -----------------
__global__ __launch_bounds__(256)
void k_agg(const float* __restrict__ hlin, const float* __restrict__ bias,
           float* __restrict__ hout, float* __restrict__ stats, int do_stats) {
    int lane = threadIdx.x & 31;
    int warp = threadIdx.x >> 5;
    int gw = blockIdx.x * 8 + warp;
    int nw = gridDim.x * 8;

    const float4* h4 = (const float4*)hlin;
    float4 b4 = ((const float4*)bias)[lane];

    float4 s1 = make_float4(0.f, 0.f, 0.f, 0.f);
    float4 s2 = make_float4(0.f, 0.f, 0.f, 0.f);

    for (int n = gw; n < NN; n += nw) {
        int beg = g_rowptr[n], end = g_rowptr[n + 1];
        float4 acc = make_float4(0.f, 0.f, 0.f, 0.f);
        int e = beg;
        while (e < end) {
            int m2 = end - e; if (m2 > 8) m2 = 8;
            int2 cw[8];
#pragma unroll
            for (int j = 0; j < 8; j++)
                if (j < m2) cw[j] = g_cw[e + j];
#pragma unroll
            for (int j = 0; j < 8; j++)
                if (j < m2) {
                    float4 v = h4[(size_t)cw[j].x * 32 + lane];
                    float w = __int_as_float(cw[j].y);
                    acc.x += v.x * w; acc.y += v.y * w;
                    acc.z += v.z * w; acc.w += v.w * w;
                }
            e += m2;
        }
        float sw = g_selfw[n];
        float4 sf = h4[(size_t)n * 32 + lane];
        float4 o;
        o.x = acc.x + sf.x * sw + b4.x;
        o.y = acc.y + sf.y * sw + b4.y;
        o.z = acc.z + sf.z * sw + b4.z;
        o.w = acc.w + sf.w * sw + b4.w;
        ((float4*)hout)[(size_t)n * 32 + lane] = o;
        if (do_stats) {
            s1.x += o.x; s1.y += o.y; s1.z += o.z; s1.w += o.w;
            s2.x += o.x * o.x; s2.y += o.y * o.y;
            s2.z += o.z * o.z; s2.w += o.w * o.w;
        }
    }

    if (do_stats) {
        __shared__ float red[8][2 * HH];
        float* r = red[warp];
        int c = lane * 4;
        r[c] = s1.x; r[c + 1] = s1.y; r[c + 2] = s1.z; r[c + 3] = s1.w;
        r[HH + c] = s2.x; r[HH + c + 1] = s2.y;
        r[HH + c + 2] = s2.z; r[HH + c + 3] = s2.w;
        __syncthreads();
        int t = threadIdx.x;
        float s = 0.f;
#pragma unroll
        for (int w2 = 0; w2 < 8; w2++) s += red[w2][t];
        atomicAdd(&stats[t], s);
    }
}

// ---------------- global mean pool (batch sorted) ---------------------------
__device__ __forceinline__ int lowerb(const int* a, int n, int key) {
    int lo = 0, hi = n;
    while (lo < hi) {
        int m = (lo + hi) >> 1;
        if (a[m] < key) lo = m + 1; else hi = m;
    }
    return lo;
}

__global__ void k_pool(const float* __restrict__ h, const int* __restrict__ batch) {
    __shared__ float red[4][HH];
    int g = blockIdx.x;
    int c = threadIdx.x & 127;
    int sub = threadIdx.x >> 7;
    int lo = lowerb(batch, NN, g);
    int hi = lowerb(batch, NN, g + 1);
    float s = 0.f;
    for (int i = lo + sub; i < hi; i += 4) s += h[(size_t)i * HH + c];
    red[sub][c] = s;
    __syncthreads();
    if (sub == 0) {
        float tot = red[0][c] + red[1][c] + red[2][c] + red[3][c];
        int cnt = hi - lo;
        g_pooled[g * HH + c] = tot / (float)(cnt > 0 ? cnt : 1);
    }
}

// ---------------- prediction head -------------------------------------------
__global__ void k_head_gemm(const float* __restrict__ X, const float* __restrict__ W,
                            const float* __restrict__ b, float* __restrict__ Y,
                            int relu) {
    __shared__ float xs[HH];
    int g = blockIdx.x, c = threadIdx.x;
    xs[c] = X[g * HH + c];
    __syncthreads();
    float acc = b[c];
#pragma unroll
    for (int k = 0; k < HH; k++) acc += xs[k] * W[k * HH + c];
    if (relu) acc = fmaxf(acc, 0.f);
    Y[g * HH + c] = acc;
}

__global__ void k_headbn(const float* __restrict__ gamma, const float* __restrict__ beta) {
    int c = threadIdx.x;
    float s = 0.f, s2 = 0.f;
    for (int g = 0; g < GG; g++) {
        float v = g_z1[g * HH + c];
        s += v; s2 += v * v;
    }
    float mu = s / (float)GG;
    float var = s2 / (float)GG - mu * mu;
    float sc = rsqrtf(var + EPS) * gamma[c];
    float sh = beta[c] - mu * sc;
    for (int g = 0; g < GG; g++) {
        float v = g_z1[g * HH + c] * sc + sh;
        g_z1[g * HH + c] = fmaxf(v, 0.f);
    }
}

__global__ void k_head_out(const float* __restrict__ X, const float* __restrict__ W,
                           const float* __restrict__ b, float* __restrict__ Y) {
    __shared__ float xs[HH];
    int g = blockIdx.x, t = threadIdx.x;
    for (int i = t; i < HH; i += 32) xs[i] = X[g * HH + i];
    __syncthreads();
    if (t < OUTC) {
        float acc = b[t];
#pragma unroll
        for (int k = 0; k < HH; k++) acc += xs[k] * W[k * OUTC + t];
        Y[g * OUTC + t] = acc;
    }
}

// ---------------- launch ----------------------------------------------------
extern "C" void kernel_launch(void* const* d_in, const int* in_sizes, int n_in,
                              void* d_out, int out_size) {
    const float* x        = (const float*)d_in[0];
    const int*   eidx     = (const int*)  d_in[1];
    const int*   batch    = (const int*)  d_in[2];
    const float* conv_W   = (const float*)d_in[3];
    const float* conv_b   = (const float*)d_in[4];
    const float* bn_gamma = (const float*)d_in[5];
    const float* bn_beta  = (const float*)d_in[6];
    const float* head_W1  = (const float*)d_in[7];
    const float* head_b1  = (const float*)d_in[8];
    const float* head_bng = (const float*)d_in[9];
    const float* head_bnb = (const float*)d_in[10];
    const float* head_W2  = (const float*)d_in[11];
    const float* head_b2  = (const float*)d_in[12];
    const float* head_W3  = (const float*)d_in[13];
    const float* head_b3  = (const float*)d_in[14];
    float* out = (float*)d_out;

    const int* src = eidx;
    const int* dst = eidx + EE;

    float *buf, *lin, *pooled, *z1, *z2, *stats;
    cudaGetSymbolAddress((void**)&buf,    g_buf);
    cudaGetSymbolAddress((void**)&lin,    g_lin);
    cudaGetSymbolAddress((void**)&pooled, g_pooled);
    cudaGetSymbolAddress((void**)&z1,     g_z1);
    cudaGetSymbolAddress((void**)&z2,     g_z2);
    cudaGetSymbolAddress((void**)&stats,  g_stats);

    cudaFuncSetAttribute(k_gemm, cudaFuncAttributeMaxDynamicSharedMemorySize, SMEM_TC);

    // one side stream + fork/join events (created once; host-side only)
    static cudaStream_t s2 = nullptr;
    static cudaEvent_t evRoot = nullptr, evJoin = nullptr;
    if (!s2) {
        cudaStreamCreateWithFlags(&s2, cudaStreamNonBlocking);
        cudaEventCreateWithFlags(&evRoot, cudaEventDisableTiming);
        cudaEventCreateWithFlags(&evJoin, cudaEventDisableTiming);
    }

    // --- fork: graph preprocessing on s2, GEMM L0 on main (independent) ---
    cudaEventRecord(evRoot, 0);
    cudaStreamWaitEvent(s2, evRoot, 0);

    k_zero_counts<<<(NN + 511) / 512, 512, 0, s2>>>();            // launch 1
    k_hist<<<(EE / 4 + 255) / 256, 256, 0, s2>>>(dst);            // launch 2
    k_scan_local<<<NPART, 512, 0, s2>>>();                        // launch 3
    k_gemm<<<GEMM_GRID, 256, SMEM_TC>>>(x, conv_W, lin,           // launch 4 (profiled)
                                        nullptr, nullptr, nullptr, 0);
    k_scan_part<<<1, 128, 0, s2>>>();                             // launch 5
    k_scan_add<<<(NN + 511) / 512, 512, 0, s2>>>();               // launch 6
    k_dinv<<<(NN + 255) / 256, 256, 0, s2>>>();                   // launch 7
    k_scatter<<<(EE + 255) / 256, 256, 0, s2>>>(src, dst);        // launch 8

    cudaEventRecord(evJoin, s2);
    cudaStreamWaitEvent(0, evJoin, 0);

    // --- GCN layers (L0 GEMM already issued above) ---
    k_agg<<<1024, 256>>>(lin, conv_b, buf, stats, 1);
    for (int l = 1; l < LL; l++) {
        const float* st_in = stats + (l - 1) * 2 * HH;
        const float* ga = bn_gamma + (l - 1) * HH;
        const float* be = bn_beta + (l - 1) * HH;
        k_gemm<<<GEMM_GRID, 256, SMEM_TC>>>(buf, conv_W + l * HH * HH, lin,
                                            st_in, ga, be, 1);
        float* st_out = (l < LL - 1) ? stats + l * 2 * HH : nullptr;
        k_agg<<<1024, 256>>>(lin, conv_b + l * HH, buf, st_out, l < LL - 1 ? 1 : 0);
    }

    // --- pool + head ---
    k_pool<<<GG, 512>>>(buf, batch);
    k_head_gemm<<<GG, HH>>>(pooled, head_W1, head_b1, z1, 0);
    k_headbn<<<1, HH>>>(head_bng, head_bnb);
    k_head_gemm<<<GG, HH>>>(z1, head_W2, head_b2, z2, 1);
    k_head_out<<<GG, 32>>>(z2, head_W3, head_b3, out);
}